// round 2
// baseline (speedup 1.0000x reference)
#include <cuda_runtime.h>
#include <cuda_bf16.h>

// Problem constants (fixed by the dataset instance)
#define B_   8
#define C_   64
#define H_   96
#define W_   96
#define O_   64
#define KH_  3
#define KW_  3
#define K_   9          // KH*KW
#define HO_  96
#define WO_  96
#define Q_   (HO_ * WO_)       // 9216
#define NTOT (B_ * Q_)         // 73728
#define CK_  (C_ * K_)         // 576

// Scratch: val[ck][n] with ck = c*9+k, n = b*Q+q  (576 * 73728 floats = ~170MB)
__device__ float g_val[(size_t)CK_ * NTOT];

// ---------------------------------------------------------------------------
// Kernel A: deformable im2col. One thread per (b, k, q). Computes the 4
// bilinear tap indices + weights once, then loops over the 64 channels.
// ---------------------------------------------------------------------------
__global__ __launch_bounds__(256) void deform_im2col_kernel(
    const float* __restrict__ input,   // [B][C][H][W]
    const float* __restrict__ offset,  // [B][2K][Ho][Wo]
    const float* __restrict__ mask)    // [B][K][Ho][Wo]
{
    int idx = blockIdx.x * blockDim.x + threadIdx.x;   // b*K*Q total
    int q = idx % Q_;
    int t = idx / Q_;
    int k = t % K_;
    int b = t / K_;

    int ho = q / WO_;
    int wo = q % WO_;
    int ky = k / KW_;
    int kx = k % KW_;

    float offy = offset[((size_t)(b * 2 * K_ + 2 * k)) * Q_ + q];
    float offx = offset[((size_t)(b * 2 * K_ + 2 * k + 1)) * Q_ + q];
    float m    = mask[((size_t)(b * K_ + k)) * Q_ + q];

    float y = (float)(ho - 1 + ky) + offy;   // stride 1, pad 1, dil 1
    float x = (float)(wo - 1 + kx) + offx;

    float y0f = floorf(y);
    float x0f = floorf(x);
    int y0 = (int)y0f;
    int x0 = (int)x0f;
    int y1 = y0 + 1;
    int x1 = x0 + 1;
    float wy = y - y0f;
    float wx = x - x0f;

    float vy0 = (y0 >= 0 && y0 < H_) ? 1.0f : 0.0f;
    float vy1 = (y1 >= 0 && y1 < H_) ? 1.0f : 0.0f;
    float vx0 = (x0 >= 0 && x0 < W_) ? 1.0f : 0.0f;
    float vx1 = (x1 >= 0 && x1 < W_) ? 1.0f : 0.0f;

    // fold mask + validity into the 4 bilinear weights
    float w00 = (1.0f - wy) * (1.0f - wx) * m * vy0 * vx0;
    float w01 = (1.0f - wy) * wx          * m * vy0 * vx1;
    float w10 = wy          * (1.0f - wx) * m * vy1 * vx0;
    float w11 = wy          * wx          * m * vy1 * vx1;

    int y0c = min(max(y0, 0), H_ - 1);
    int y1c = min(max(y1, 0), H_ - 1);
    int x0c = min(max(x0, 0), W_ - 1);
    int x1c = min(max(x1, 0), W_ - 1);

    int i00 = y0c * W_ + x0c;
    int i01 = y0c * W_ + x1c;
    int i10 = y1c * W_ + x0c;
    int i11 = y1c * W_ + x1c;

    const float* base = input + (size_t)b * C_ * H_ * W_;
    float* outp = g_val + (size_t)k * NTOT + (size_t)b * Q_ + q;

    #pragma unroll 8
    for (int c = 0; c < C_; ++c) {
        const float* p = base + (size_t)c * (H_ * W_);
        float v = w00 * p[i00] + w01 * p[i01] + w10 * p[i10] + w11 * p[i11];
        outp[(size_t)c * K_ * NTOT] = v;
    }
}

// ---------------------------------------------------------------------------
// Kernel B: SGEMM  out[o][n] = sum_ck W[o][ck] * val[ck][n] + bias[o]
//   M=64, K=576, N=73728.  Block tile 64x128, BK=16, thread tile 8x4,
//   256 threads. Epilogue scatters into [b][o][q] layout (b constant/block
//   since Q is divisible by BN).
// ---------------------------------------------------------------------------
__global__ __launch_bounds__(256) void deform_gemm_kernel(
    const float* __restrict__ Wg,    // [O][CK] = [64][576]
    const float* __restrict__ bias,  // [O]
    float* __restrict__ out)         // [B][O][Q]
{
    __shared__ float As[16][64];     // [kk][o]
    __shared__ float Bs[16][128];    // [kk][n]

    int tid = threadIdx.x;
    int nbase = blockIdx.x * 128;

    int trow = tid >> 5;     // 0..7
    int tcol = tid & 31;     // 0..31
    int m0 = trow * 8;
    int n0 = tcol * 4;

    float acc[8][4];
    #pragma unroll
    for (int i = 0; i < 8; ++i)
        #pragma unroll
        for (int j = 0; j < 4; ++j)
            acc[i][j] = 0.0f;

    for (int k0 = 0; k0 < CK_; k0 += 16) {
        // load weight tile: As[kk][o]
        #pragma unroll
        for (int i = 0; i < 4; ++i) {
            int lin = tid + i * 256;      // 0..1023
            int kk = lin >> 6;
            int o  = lin & 63;
            As[kk][o] = Wg[(size_t)o * CK_ + k0 + kk];
        }
        // load val tile: Bs[kk][n]  (coalesced, 128-float rows)
        #pragma unroll
        for (int i = 0; i < 8; ++i) {
            int lin = tid + i * 256;      // 0..2047
            int kk = lin >> 7;
            int n  = lin & 127;
            Bs[kk][n] = g_val[(size_t)(k0 + kk) * NTOT + nbase + n];
        }
        __syncthreads();

        #pragma unroll
        for (int kk = 0; kk < 16; ++kk) {
            float a[8], bb[4];
            #pragma unroll
            for (int i = 0; i < 8; ++i) a[i] = As[kk][m0 + i];
            #pragma unroll
            for (int j = 0; j < 4; ++j) bb[j] = Bs[kk][n0 + j];
            #pragma unroll
            for (int i = 0; i < 8; ++i)
                #pragma unroll
                for (int j = 0; j < 4; ++j)
                    acc[i][j] = fmaf(a[i], bb[j], acc[i][j]);
        }
        __syncthreads();
    }

    // epilogue: n = nbase + n0 + j ; b = n / Q, q = n % Q (b constant per block)
    int b = nbase / Q_;
    int qbase = nbase % Q_;
    #pragma unroll
    for (int i = 0; i < 8; ++i) {
        int o = m0 + i;
        float bi = bias[o];
        float4 v = make_float4(acc[i][0] + bi, acc[i][1] + bi,
                               acc[i][2] + bi, acc[i][3] + bi);
        *(float4*)&out[((size_t)(b * O_ + o)) * Q_ + qbase + n0] = v;
    }
}

// ---------------------------------------------------------------------------
extern "C" void kernel_launch(void* const* d_in, const int* in_sizes, int n_in,
                              void* d_out, int out_size)
{
    const float* input  = (const float*)d_in[0];  // [8,64,96,96]
    const float* offset = (const float*)d_in[1];  // [8,18,96,96]
    const float* mask   = (const float*)d_in[2];  // [8,9,96,96]
    const float* weight = (const float*)d_in[3];  // [64,64,3,3]
    const float* bias   = (const float*)d_in[4];  // [64]
    float* out = (float*)d_out;                   // [8,64,96,96]

    // Kernel A: B*K*Q threads = 663552 -> 2592 blocks of 256
    int totalA = B_ * K_ * Q_;
    deform_im2col_kernel<<<totalA / 256, 256>>>(input, offset, mask);

    // Kernel B: NTOT/128 = 576 blocks of 256 threads
    deform_gemm_kernel<<<NTOT / 128, 256>>>(weight, bias, out);
}

// round 4
// speedup vs baseline: 1.8254x; 1.8254x over previous
#include <cuda_runtime.h>

// Fixed problem shape
#define B_   8
#define C_   64
#define H_   96
#define W_   96
#define O_   64
#define K_   9
#define Q_   (H_ * W_)        // 9216
#define HW_  (H_ * W_)
#define TILE 128              // pixels per block
#define NE   (K_ * TILE)      // 1152 sampling entries per block
#define THREADS 256
#define NBLK (B_ * Q_ / TILE) // 576

// ---------------------------------------------------------------------------
// Fused DCNv2: per block = (batch b, 128 contiguous output pixels).
// Phase 1: bilinear sampling coords/weights for 9 taps x 128 px -> smem.
// Phase 2: loop c = 0..63: gather Bs[9][128] from input (L2-resident),
//          load As[9][64] weight slice, 9 K-steps of f32x2 packed FMA.
// ---------------------------------------------------------------------------
__global__ __launch_bounds__(256) void dcn_fused_kernel(
    const float* __restrict__ input,   // [B][C][H][W]
    const float* __restrict__ offset,  // [B][2K][Ho][Wo]
    const float* __restrict__ mask,    // [B][K][Ho][Wo]
    const float* __restrict__ weight,  // [O][C][KH][KW]
    const float* __restrict__ bias,    // [O]
    float* __restrict__ out)           // [B][O][Ho][Wo]
{
    __shared__ __align__(16) int4   s_idx[NE];       // 18.4 KB
    __shared__ __align__(16) float4 s_wt[NE];        // 18.4 KB
    __shared__ __align__(16) float  As[K_][O_];      // 2.3 KB
    __shared__ __align__(16) float  Bs[K_][TILE];    // 4.6 KB

    const int tid   = threadIdx.x;
    const int bq    = blockIdx.x;
    const int b     = bq / (Q_ / TILE);              // /72
    const int qbase = (bq % (Q_ / TILE)) * TILE;

    // ---------------- Phase 1: sampling coordinates (channel-invariant) ----
    for (int e = tid; e < NE; e += THREADS) {
        int k = e >> 7;            // e / 128
        int n = e & (TILE - 1);
        int q = qbase + n;
        int ho = q / W_;
        int wo = q - ho * W_;
        int ky = k / 3;
        int kx = k - ky * 3;

        float offy = offset[((size_t)(b * 2 * K_ + 2 * k)) * Q_ + q];
        float offx = offset[((size_t)(b * 2 * K_ + 2 * k + 1)) * Q_ + q];
        float m    = mask[((size_t)(b * K_ + k)) * Q_ + q];

        float y = (float)(ho - 1 + ky) + offy;       // stride 1, pad 1, dil 1
        float x = (float)(wo - 1 + kx) + offx;

        float y0f = floorf(y), x0f = floorf(x);
        int y0 = (int)y0f, x0 = (int)x0f;
        int y1 = y0 + 1,   x1 = x0 + 1;
        float wy = y - y0f, wx = x - x0f;

        float vy0 = (y0 >= 0 && y0 < H_) ? 1.0f : 0.0f;
        float vy1 = (y1 >= 0 && y1 < H_) ? 1.0f : 0.0f;
        float vx0 = (x0 >= 0 && x0 < W_) ? 1.0f : 0.0f;
        float vx1 = (x1 >= 0 && x1 < W_) ? 1.0f : 0.0f;

        float w00 = (1.0f - wy) * (1.0f - wx) * m * vy0 * vx0;
        float w01 = (1.0f - wy) * wx          * m * vy0 * vx1;
        float w10 = wy          * (1.0f - wx) * m * vy1 * vx0;
        float w11 = wy          * wx          * m * vy1 * vx1;

        int y0c = min(max(y0, 0), H_ - 1);
        int y1c = min(max(y1, 0), H_ - 1);
        int x0c = min(max(x0, 0), W_ - 1);
        int x1c = min(max(x1, 0), W_ - 1);

        s_idx[e] = make_int4(y0c * W_ + x0c, y0c * W_ + x1c,
                             y1c * W_ + x0c, y1c * W_ + x1c);
        s_wt[e]  = make_float4(w00, w01, w10, w11);
    }

    // ---------------- Phase 2: main loop over channels ---------------------
    const int trow = tid >> 5;          // 0..7  -> o block of 8
    const int tcol = tid & 31;          // 0..31 -> n block of 4
    const int m0 = trow * 8;
    const int n0 = tcol * 4;

    // acc[p][j]: f32x2 pair (o = m0+2p, m0+2p+1) for n = n0+j
    unsigned long long acc[4][4];
    #pragma unroll
    for (int p = 0; p < 4; ++p)
        #pragma unroll
        for (int j = 0; j < 4; ++j)
            acc[p][j] = 0ULL;

    const float* inb = input + (size_t)b * C_ * HW_;

    for (int c = 0; c < C_; ++c) {
        __syncthreads();   // prev GEMM done reading As/Bs (and phase-1 ready at c=0)

        // load weight slice As[k][o] = weight[o][c][k]
        for (int lin = tid; lin < O_ * K_; lin += THREADS) {
            int o = lin / K_;
            int k = lin - o * K_;
            As[k][o] = weight[(size_t)o * (C_ * K_) + c * K_ + k];
        }

        // gather Bs[k][n] via bilinear sampling from channel c
        const float* p = inb + (size_t)c * HW_;
        float* bs = &Bs[0][0];
        for (int e = tid; e < NE; e += THREADS) {
            int4   ii = s_idx[e];
            float4 ww = s_wt[e];
            float v = ww.x * __ldg(&p[ii.x]) + ww.y * __ldg(&p[ii.y])
                    + ww.z * __ldg(&p[ii.z]) + ww.w * __ldg(&p[ii.w]);
            bs[e] = v;
        }

        __syncthreads();

        // 9 K-steps of packed FMA
        #pragma unroll
        for (int kk = 0; kk < K_; ++kk) {
            const unsigned long long* ap =
                (const unsigned long long*)&As[kk][m0];   // 32B aligned
            unsigned long long a0 = ap[0], a1 = ap[1], a2 = ap[2], a3 = ap[3];
            float4 bb = *(const float4*)&Bs[kk][n0];

            unsigned long long bd0, bd1, bd2, bd3;
            asm("mov.b64 %0, {%1, %1};" : "=l"(bd0) : "f"(bb.x));
            asm("mov.b64 %0, {%1, %1};" : "=l"(bd1) : "f"(bb.y));
            asm("mov.b64 %0, {%1, %1};" : "=l"(bd2) : "f"(bb.z));
            asm("mov.b64 %0, {%1, %1};" : "=l"(bd3) : "f"(bb.w));

            #pragma unroll
            for (int j = 0; j < 4; ++j) {
                unsigned long long bd = (j == 0) ? bd0 : (j == 1) ? bd1
                                       : (j == 2) ? bd2 : bd3;
                asm("fma.rn.f32x2 %0, %1, %2, %0;" : "+l"(acc[0][j]) : "l"(a0), "l"(bd));
                asm("fma.rn.f32x2 %0, %1, %2, %0;" : "+l"(acc[1][j]) : "l"(a1), "l"(bd));
                asm("fma.rn.f32x2 %0, %1, %2, %0;" : "+l"(acc[2][j]) : "l"(a2), "l"(bd));
                asm("fma.rn.f32x2 %0, %1, %2, %0;" : "+l"(acc[3][j]) : "l"(a3), "l"(bd));
            }
        }
    }

    // ---------------- Epilogue: unpack, add bias, store --------------------
    #pragma unroll
    for (int p = 0; p < 4; ++p) {
        float lo[4], hi[4];
        #pragma unroll
        for (int j = 0; j < 4; ++j) {
            asm("mov.b64 {%0, %1}, %2;" : "=f"(lo[j]), "=f"(hi[j]) : "l"(acc[p][j]));
        }
        int o_lo = m0 + 2 * p;
        int o_hi = o_lo + 1;
        float blo = bias[o_lo];
        float bhi = bias[o_hi];
        float4 vlo = make_float4(lo[0] + blo, lo[1] + blo, lo[2] + blo, lo[3] + blo);
        float4 vhi = make_float4(hi[0] + bhi, hi[1] + bhi, hi[2] + bhi, hi[3] + bhi);
        *(float4*)&out[((size_t)(b * O_ + o_lo)) * Q_ + qbase + n0] = vlo;
        *(float4*)&out[((size_t)(b * O_ + o_hi)) * Q_ + qbase + n0] = vhi;
    }
}

// ---------------------------------------------------------------------------
extern "C" void kernel_launch(void* const* d_in, const int* in_sizes, int n_in,
                              void* d_out, int out_size)
{
    const float* input  = (const float*)d_in[0];  // [8,64,96,96]
    const float* offset = (const float*)d_in[1];  // [8,18,96,96]
    const float* mask   = (const float*)d_in[2];  // [8,9,96,96]
    const float* weight = (const float*)d_in[3];  // [64,64,3,3]
    const float* bias   = (const float*)d_in[4];  // [64]
    float* out = (float*)d_out;                   // [8,64,96,96]

    dcn_fused_kernel<<<NBLK, THREADS>>>(input, offset, mask, weight, bias, out);
}